// round 3
// baseline (speedup 1.0000x reference)
#include <cuda_runtime.h>
#include <math.h>

#define B_DIM 64
#define K_DIM 128
#define H_DIM 64
#define W_DIM 64
#define PLANE (H_DIM * W_DIM)          // 4096 floats
#define PLANE4 (PLANE / 4)             // 1024 float4
#define N_PLANES (B_DIM * K_DIM)       // 8192
#define N_BOXES 256
#define ALPHA 1.0f
#define BETA 0.5f
#define NPART 32

#define WARPS_PER_BLOCK 8
#define N_LOC_BLOCKS (N_BOXES / WARPS_PER_BLOCK)     // 32
#define N_CLS_BLOCKS (N_PLANES / WARPS_PER_BLOCK)    // 1024
#define N_BLOCKS (N_LOC_BLOCKS + N_CLS_BLOCKS)       // 1056

// Zero-initialized device globals (reset by the last block each run).
__device__ float g_cls_parts[NPART];
__device__ float g_loc_parts[NPART];
__device__ unsigned int g_done_count;

__device__ __forceinline__ float softplus_f(float x) {
    float ax = fabsf(x);
    return log1pf(expf(-ax)) + fmaxf(x, 0.0f);
}

__global__ __launch_bounds__(256) void fused_loss_kernel(
    const float* __restrict__ cams,
    const float* __restrict__ concepts_gt,
    const int* __restrict__ box_b,
    const int* __restrict__ box_c,
    const int* __restrict__ y0v,
    const int* __restrict__ y1v,
    const int* __restrict__ x0v,
    const int* __restrict__ x1v,
    float* __restrict__ out)
{
    int t = threadIdx.x;
    int wid = t >> 5, lid = t & 31;

    if (blockIdx.x < N_LOC_BLOCKS) {
        // -------- loc path: one WARP per box --------
        int box = blockIdx.x * WARPS_PER_BLOCK + wid;
        int b = box_b[box];
        int c = box_c[box];
        int y0 = y0v[box], y1 = y1v[box], x0 = x0v[box], x1 = x1v[box];

        const float4* p = reinterpret_cast<const float4*>(
            cams + ((size_t)b * K_DIM + c) * PLANE);

        float inside = 0.0f, outside = 0.0f;
#pragma unroll
        for (int j = 0; j < 32; j++) {
            int u = lid + 32 * j;        // float4 index in plane
            float4 v = p[u];
            int row = u >> 4;            // 16 float4 per row (W=64)
            int col0 = (u & 15) << 2;
            bool rin = (row >= y0) && (row < y1);
            float vals[4] = {v.x, v.y, v.z, v.w};
#pragma unroll
            for (int q = 0; q < 4; q++) {
                int col = col0 + q;
                float s = 1.0f / (1.0f + expf(-vals[q]));
                bool in = rin && (col >= x0) && (col < x1);
                float d = s - 1.0f;
                if (in) inside += d * d;
                else    outside += s * s;
            }
        }
#pragma unroll
        for (int off = 16; off > 0; off >>= 1) {
            inside  += __shfl_xor_sync(0xFFFFFFFFu, inside, off);
            outside += __shfl_xor_sync(0xFFFFFFFFu, outside, off);
        }
        if (lid == 0) {
            float area = (float)((y1 - y0) * (x1 - x0));
            const float eps = 1e-6f;
            float loss = inside / (area + eps) + outside / ((float)PLANE - area + eps);
            atomicAdd(&g_loc_parts[box & (NPART - 1)], loss);
        }
    } else {
        // -------- cls path: one WARP per (b,k) plane --------
        int plane = (blockIdx.x - N_LOC_BLOCKS) * WARPS_PER_BLOCK + wid;
        const float4* p = reinterpret_cast<const float4*>(cams + (size_t)plane * PLANE);

        float m = -INFINITY;
#pragma unroll
        for (int j = 0; j < 32; j++) {
            float4 v = p[lid + 32 * j];
            m = fmaxf(m, fmaxf(fmaxf(v.x, v.y), fmaxf(v.z, v.w)));
        }
#pragma unroll
        for (int off = 16; off > 0; off >>= 1)
            m = fmaxf(m, __shfl_xor_sync(0xFFFFFFFFu, m, off));
        if (lid == 0) {
            float y = concepts_gt[plane];
            float bce = y * softplus_f(-m) + (1.0f - y) * softplus_f(m);
            atomicAdd(&g_cls_parts[plane & (NPART - 1)], bce);
        }
    }

    // -------- last-block finalize --------
    __syncthreads();
    if (t == 0) {
        __threadfence();
        unsigned int prev = atomicAdd(&g_done_count, 1u);
        if (prev == N_BLOCKS - 1) {
            float cls = 0.0f, loc = 0.0f;
#pragma unroll
            for (int i = 0; i < NPART; i++) {
                cls += g_cls_parts[i];
                loc += g_loc_parts[i];
                g_cls_parts[i] = 0.0f;
                g_loc_parts[i] = 0.0f;
            }
            out[0] = ALPHA * (cls / (float)N_PLANES) + BETA * (loc / (float)N_BOXES);
            g_done_count = 0u;   // reset for next graph replay
        }
    }
}

extern "C" void kernel_launch(void* const* d_in, const int* in_sizes, int n_in,
                              void* d_out, int out_size) {
    const float* cams        = (const float*)d_in[0];
    const float* concepts_gt = (const float*)d_in[1];
    const int*   box_b       = (const int*)d_in[2];
    const int*   box_c       = (const int*)d_in[3];
    const int*   y0          = (const int*)d_in[4];
    const int*   y1          = (const int*)d_in[5];
    const int*   x0          = (const int*)d_in[6];
    const int*   x1          = (const int*)d_in[7];
    float* out = (float*)d_out;

    fused_loss_kernel<<<N_BLOCKS, 256>>>(cams, concepts_gt, box_b, box_c,
                                         y0, y1, x0, x1, out);
}

// round 4
// speedup vs baseline: 1.1439x; 1.1439x over previous
#include <cuda_runtime.h>
#include <math.h>

#define B_DIM 64
#define K_DIM 128
#define H_DIM 64
#define W_DIM 64
#define PLANE (H_DIM * W_DIM)          // 4096 floats
#define N_PLANES (B_DIM * K_DIM)       // 8192
#define N_BOXES 256
#define ALPHA 1.0f
#define BETA 0.5f
#define NPART 32
#define PART_STRIDE 32                 // 32 floats = 128B between slots

// Zero-initialized device globals; last loc block resets them each run.
__device__ float g_cls_parts[NPART * PART_STRIDE];
__device__ float g_loc_parts[NPART * PART_STRIDE];
__device__ unsigned int g_done_count;

__device__ __forceinline__ float softplus_f(float x) {
    float ax = fabsf(x);
    return log1pf(expf(-ax)) + fmaxf(x, 0.0f);
}

// One CTA per (b,k) plane: max over 4096 floats, BCE-with-logits, accumulate.
// (R1-proven streaming shape: ~6.1 TB/s)
__global__ __launch_bounds__(256) void cls_kernel(const float* __restrict__ cams,
                                                  const float* __restrict__ concepts_gt) {
    int plane = blockIdx.x;
    const float4* p = reinterpret_cast<const float4*>(cams + (size_t)plane * PLANE);

    int t = threadIdx.x;
    float m = -INFINITY;
#pragma unroll
    for (int i = 0; i < 4; i++) {
        float4 v = p[i * 256 + t];
        m = fmaxf(m, fmaxf(fmaxf(v.x, v.y), fmaxf(v.z, v.w)));
    }
#pragma unroll
    for (int off = 16; off > 0; off >>= 1)
        m = fmaxf(m, __shfl_xor_sync(0xFFFFFFFFu, m, off));

    __shared__ float sm[8];
    int wid = t >> 5, lid = t & 31;
    if (lid == 0) sm[wid] = m;
    __syncthreads();
    if (t == 0) {
        float bm = sm[0];
#pragma unroll
        for (int w = 1; w < 8; w++) bm = fmaxf(bm, sm[w]);
        float y = concepts_gt[plane];
        float bce = y * softplus_f(-bm) + (1.0f - y) * softplus_f(bm);
        atomicAdd(&g_cls_parts[(plane & (NPART - 1)) * PART_STRIDE], bce);
    }
}

// One CTA per box; last finishing block also finalizes (cls kernel already
// completed — kernel boundary orders its atomics).
__global__ __launch_bounds__(256) void loc_finalize_kernel(
    const float* __restrict__ cams,
    const int* __restrict__ box_b,
    const int* __restrict__ box_c,
    const int* __restrict__ y0v,
    const int* __restrict__ y1v,
    const int* __restrict__ x0v,
    const int* __restrict__ x1v,
    float* __restrict__ out)
{
    int box = blockIdx.x;
    int b = box_b[box];
    int c = box_c[box];
    int y0 = y0v[box], y1 = y1v[box], x0 = x0v[box], x1 = x1v[box];

    const float4* p = reinterpret_cast<const float4*>(
        cams + ((size_t)b * K_DIM + c) * PLANE);

    int t = threadIdx.x;
    float inside = 0.0f, outside = 0.0f;
#pragma unroll
    for (int i = 0; i < 4; i++) {
        int u = i * 256 + t;            // float4 index within plane [0,1024)
        float4 v = p[u];
        int row = u >> 4;               // 16 float4 per row (W=64)
        int col0 = (u & 15) << 2;
        float vals[4] = {v.x, v.y, v.z, v.w};
        bool rin = (row >= y0) && (row < y1);
#pragma unroll
        for (int j = 0; j < 4; j++) {
            int col = col0 + j;
            float s = 1.0f / (1.0f + expf(-vals[j]));
            bool in = rin && (col >= x0) && (col < x1);
            float d = s - 1.0f;
            if (in) inside += d * d;
            else    outside += s * s;
        }
    }
#pragma unroll
    for (int off = 16; off > 0; off >>= 1) {
        inside  += __shfl_xor_sync(0xFFFFFFFFu, inside, off);
        outside += __shfl_xor_sync(0xFFFFFFFFu, outside, off);
    }
    __shared__ float si[8], so[8];
    int wid = t >> 5, lid = t & 31;
    if (lid == 0) { si[wid] = inside; so[wid] = outside; }
    __syncthreads();
    if (t == 0) {
        float ti = 0.0f, to = 0.0f;
#pragma unroll
        for (int w = 0; w < 8; w++) { ti += si[w]; to += so[w]; }
        float area = (float)((y1 - y0) * (x1 - x0));
        const float eps = 1e-6f;
        float loss = ti / (area + eps) + to / ((float)PLANE - area + eps);
        atomicAdd(&g_loc_parts[(box & (NPART - 1)) * PART_STRIDE], loss);

        // ---- last-block finalize ----
        __threadfence();
        unsigned int prev = atomicAdd(&g_done_count, 1u);
        if (prev == N_BOXES - 1) {
            float cls = 0.0f, loc = 0.0f;
#pragma unroll
            for (int i = 0; i < NPART; i++) {
                cls += g_cls_parts[i * PART_STRIDE];
                loc += g_loc_parts[i * PART_STRIDE];
                g_cls_parts[i * PART_STRIDE] = 0.0f;
                g_loc_parts[i * PART_STRIDE] = 0.0f;
            }
            out[0] = ALPHA * (cls / (float)N_PLANES) + BETA * (loc / (float)N_BOXES);
            g_done_count = 0u;   // reset for next graph replay
        }
    }
}

extern "C" void kernel_launch(void* const* d_in, const int* in_sizes, int n_in,
                              void* d_out, int out_size) {
    const float* cams        = (const float*)d_in[0];
    const float* concepts_gt = (const float*)d_in[1];
    const int*   box_b       = (const int*)d_in[2];
    const int*   box_c       = (const int*)d_in[3];
    const int*   y0          = (const int*)d_in[4];
    const int*   y1          = (const int*)d_in[5];
    const int*   x0          = (const int*)d_in[6];
    const int*   x1          = (const int*)d_in[7];
    float* out = (float*)d_out;

    cls_kernel<<<N_PLANES, 256>>>(cams, concepts_gt);
    loc_finalize_kernel<<<N_BOXES, 256>>>(cams, box_b, box_c, y0, y1, x0, x1, out);
}

// round 5
// speedup vs baseline: 1.2283x; 1.0738x over previous
#include <cuda_runtime.h>
#include <math.h>

#define B_DIM 64
#define K_DIM 128
#define H_DIM 64
#define W_DIM 64
#define PLANE (H_DIM * W_DIM)          // 4096 floats
#define N_PLANES (B_DIM * K_DIM)       // 8192
#define N_BOXES 256
#define ALPHA 1.0f
#define BETA 0.5f
#define NPART 32
#define PART_STRIDE 32                 // 32 floats = 128B between slots

#define LOC_SPLIT 4                    // blocks per box
#define N_LOC_BLOCKS (N_BOXES * LOC_SPLIT)   // 1024

// Zero-initialized device globals; last loc block resets them each run.
__device__ float g_cls_parts[NPART * PART_STRIDE];
__device__ float g_loc_parts[NPART * PART_STRIDE];
__device__ unsigned int g_done_count;

__device__ __forceinline__ float softplus_f(float x) {
    float ax = fabsf(x);
    return log1pf(expf(-ax)) + fmaxf(x, 0.0f);
}

// One CTA per (b,k) plane: max over 4096 floats, BCE-with-logits, accumulate.
// (Proven streaming shape: ~6.1 TB/s)
__global__ __launch_bounds__(256) void cls_kernel(const float* __restrict__ cams,
                                                  const float* __restrict__ concepts_gt) {
    int plane = blockIdx.x;
    const float4* p = reinterpret_cast<const float4*>(cams + (size_t)plane * PLANE);

    int t = threadIdx.x;
    float m = -INFINITY;
#pragma unroll
    for (int i = 0; i < 4; i++) {
        float4 v = p[i * 256 + t];
        m = fmaxf(m, fmaxf(fmaxf(v.x, v.y), fmaxf(v.z, v.w)));
    }
#pragma unroll
    for (int off = 16; off > 0; off >>= 1)
        m = fmaxf(m, __shfl_xor_sync(0xFFFFFFFFu, m, off));

    __shared__ float sm[8];
    int wid = t >> 5, lid = t & 31;
    if (lid == 0) sm[wid] = m;
    __syncthreads();
    if (t == 0) {
        float bm = sm[0];
#pragma unroll
        for (int w = 1; w < 8; w++) bm = fmaxf(bm, sm[w]);
        float y = concepts_gt[plane];
        float bce = y * softplus_f(-bm) + (1.0f - y) * softplus_f(bm);
        atomicAdd(&g_cls_parts[(plane & (NPART - 1)) * PART_STRIDE], bce);
    }
}

// LOC_SPLIT CTAs per box, each covers 1/LOC_SPLIT of the plane.
// Per-box divisions are linear in the partial sums, so each block adds its
// already-scaled contribution. Last finishing block finalizes.
__global__ __launch_bounds__(256) void loc_finalize_kernel(
    const float* __restrict__ cams,
    const int* __restrict__ box_b,
    const int* __restrict__ box_c,
    const int* __restrict__ y0v,
    const int* __restrict__ y1v,
    const int* __restrict__ x0v,
    const int* __restrict__ x1v,
    float* __restrict__ out)
{
    int box  = blockIdx.x >> 2;        // LOC_SPLIT == 4
    int part = blockIdx.x & 3;
    int b = box_b[box];
    int c = box_c[box];
    int y0 = y0v[box], y1 = y1v[box], x0 = x0v[box], x1 = x1v[box];

    const float4* p = reinterpret_cast<const float4*>(
        cams + ((size_t)b * K_DIM + c) * PLANE);

    int t = threadIdx.x;
    int u = part * 256 + t;            // float4 index within plane [0,1024)
    float4 v = p[u];
    int row = u >> 4;                  // 16 float4 per row (W=64)
    int col0 = (u & 15) << 2;
    bool rin = (row >= y0) && (row < y1);

    float inside = 0.0f, outside = 0.0f;
    float vals[4] = {v.x, v.y, v.z, v.w};
#pragma unroll
    for (int j = 0; j < 4; j++) {
        int col = col0 + j;
        float e = __expf(-vals[j]);
        float s = __fdividef(1.0f, 1.0f + e);
        bool in = rin && (col >= x0) && (col < x1);
        float d = s - 1.0f;
        if (in) inside += d * d;
        else    outside += s * s;
    }
#pragma unroll
    for (int off = 16; off > 0; off >>= 1) {
        inside  += __shfl_xor_sync(0xFFFFFFFFu, inside, off);
        outside += __shfl_xor_sync(0xFFFFFFFFu, outside, off);
    }
    __shared__ float si[8], so[8];
    int wid = t >> 5, lid = t & 31;
    if (lid == 0) { si[wid] = inside; so[wid] = outside; }
    __syncthreads();
    if (t == 0) {
        float ti = 0.0f, to = 0.0f;
#pragma unroll
        for (int w = 0; w < 8; w++) { ti += si[w]; to += so[w]; }
        float area = (float)((y1 - y0) * (x1 - x0));
        const float eps = 1e-6f;
        // Scaled partial contribution (division distributes over parts).
        float loss = ti / (area + eps) + to / ((float)PLANE - area + eps);
        atomicAdd(&g_loc_parts[(blockIdx.x & (NPART - 1)) * PART_STRIDE], loss);

        // ---- last-block finalize ----
        __threadfence();
        unsigned int prev = atomicAdd(&g_done_count, 1u);
        if (prev == N_LOC_BLOCKS - 1) {
            float cls = 0.0f, loc = 0.0f;
#pragma unroll
            for (int i = 0; i < NPART; i++) {
                cls += g_cls_parts[i * PART_STRIDE];
                loc += g_loc_parts[i * PART_STRIDE];
                g_cls_parts[i * PART_STRIDE] = 0.0f;
                g_loc_parts[i * PART_STRIDE] = 0.0f;
            }
            out[0] = ALPHA * (cls / (float)N_PLANES) + BETA * (loc / (float)N_BOXES);
            g_done_count = 0u;   // reset for next graph replay
        }
    }
}

extern "C" void kernel_launch(void* const* d_in, const int* in_sizes, int n_in,
                              void* d_out, int out_size) {
    const float* cams        = (const float*)d_in[0];
    const float* concepts_gt = (const float*)d_in[1];
    const int*   box_b       = (const int*)d_in[2];
    const int*   box_c       = (const int*)d_in[3];
    const int*   y0          = (const int*)d_in[4];
    const int*   y1          = (const int*)d_in[5];
    const int*   x0          = (const int*)d_in[6];
    const int*   x1          = (const int*)d_in[7];
    float* out = (float*)d_out;

    cls_kernel<<<N_PLANES, 256>>>(cams, concepts_gt);
    loc_finalize_kernel<<<N_LOC_BLOCKS, 256>>>(cams, box_b, box_c, y0, y1, x0, x1, out);
}